// round 8
// baseline (speedup 1.0000x reference)
#include <cuda_runtime.h>

// Apply_Mask v8 — v5 structure (2 warps/slice, 64-thread CTA, 85% occ,
// proven 35.5us) with DEFAULT-policy input reads (__ldg) instead of __ldcs:
// __ldcs marks input lines evict-first and throws away the natural
// cross-replay L2 retention (measured ~56MB/replay absorbed). Default
// eviction lets more of the 134MB input persist in the 126MB L2.
// Output stores remain evict-first (__stcs): written once, never re-read.

#define H 32
#define W 32
#define HW 1024

__global__ void __launch_bounds__(64)
apply_mask_v8(const float* __restrict__ x,
              const int* __restrict__ T,
              const int* __restrict__ drop_block_ptr,
              float* __restrict__ out)
{
    __shared__ unsigned skey[2];
    __shared__ unsigned sidx[2];

    const int tid = threadIdx.x;          // 0..63
    const int warp = tid >> 5;            // 0..1
    const int slice = blockIdx.x;
    const size_t base = (size_t)slice * HW;

    const float4* __restrict__ xin = reinterpret_cast<const float4*>(x + base);
    float4* __restrict__ o = reinterpret_cast<float4*>(out + base);

    // T load first, in flight alongside bulk loads (CTA-uniform value).
    const int t = __ldg(T + slice);

    // ---- front-batched bulk load: 4 x LDG.128 per lane, default policy ----
    float4 v[4];
#pragma unroll
    for (int j = 0; j < 4; j++)
        v[j] = __ldg(xin + j * 64 + tid);

    if (t == 0) {
        // ---- copy path: no reduction, no barriers ----
#pragma unroll
        for (int j = 0; j < 4; j++)
            __stcs(o + j * 64 + tid, v[j]);
        return;
    }

    // ---- local max (pairwise tree), then warp REDUX on ordered key ----
    float m01 = fmaxf(fmaxf(fmaxf(v[0].x, v[0].y), fmaxf(v[0].z, v[0].w)),
                      fmaxf(fmaxf(v[1].x, v[1].y), fmaxf(v[1].z, v[1].w)));
    float m23 = fmaxf(fmaxf(fmaxf(v[2].x, v[2].y), fmaxf(v[2].z, v[2].w)),
                      fmaxf(fmaxf(v[3].x, v[3].y), fmaxf(v[3].z, v[3].w)));
    float m = fmaxf(m01, m23);

    unsigned u = __float_as_uint(m);
    unsigned key = u ^ (unsigned)(((int)u >> 31) | 0x80000000);
    key = __reduce_max_sync(0xffffffffu, key);

    if ((tid & 31) == 0) skey[warp] = key;
    __syncthreads();
    key = max(skey[0], skey[1]);

    unsigned mu = key ^ (unsigned)((~((int)key >> 31)) | 0x80000000);
    const float maxf = __uint_as_float(mu);

    // ---- first-occurrence index of maxf ----
    unsigned idx = HW;
    {
        const float* vf = &v[0].x;
#pragma unroll
        for (int j = 0; j < 4; j++) {
#pragma unroll
            for (int i = 0; i < 4; i++) {
                const unsigned e = (unsigned)((j * 64 + tid) * 4 + i);
                if (vf[j * 4 + i] == maxf) idx = min(idx, e);
            }
        }
    }
    idx = __reduce_min_sync(0xffffffffu, idx);

    if ((tid & 31) == 0) sidx[warp] = idx;
    __syncthreads();
    idx = min(sidx[0], sidx[1]);

    // ---- box + lambda ----
    const int mh = (int)(idx >> 5);
    const int mw = (int)(idx & (W - 1));
    const int db = drop_block_ptr ? *drop_block_ptr : 5;
    const int half = db >> 1;

    const int h1 = max(mh - half, 0);
    const int h2 = min(mh + half, H - 1);
    const int w1 = max(mw - half, 0);
    const int w2 = min(mw + half, W - 1);

    const int area = (h2 - h1 + 1) * (w2 - w1 + 1);
    const float lam = (float)HW / (float)(HW - area);

    // element e = (j*64 + tid)*4 + i  ->  row = j*8 + (tid>>3),
    //                                     col = (tid&7)*4 + i
    const int rbase = tid >> 3;
    const int cbase = (tid & 7) * 4;

    bool in_col[4];
#pragma unroll
    for (int i = 0; i < 4; i++)
        in_col[i] = (unsigned)(cbase + i - w1) <= (unsigned)(w2 - w1);

    float row_scale[4];  // scale when in_col true: 0 inside box, lam outside
#pragma unroll
    for (int j = 0; j < 4; j++) {
        const int r = j * 8 + rbase;
        const bool in_row = (unsigned)(r - h1) <= (unsigned)(h2 - h1);
        row_scale[j] = in_row ? 0.0f : lam;
    }

    // ---- scale + store ----
#pragma unroll
    for (int j = 0; j < 4; j++) {
        float4 w4;
        w4.x = v[j].x * (in_col[0] ? row_scale[j] : lam);
        w4.y = v[j].y * (in_col[1] ? row_scale[j] : lam);
        w4.z = v[j].z * (in_col[2] ? row_scale[j] : lam);
        w4.w = v[j].w * (in_col[3] ? row_scale[j] : lam);
        __stcs(o + j * 64 + tid, w4);
    }
}

extern "C" void kernel_launch(void* const* d_in, const int* in_sizes, int n_in,
                              void* d_out, int out_size)
{
    const float* x = (const float*)d_in[0];
    const int* T = (const int*)d_in[1];
    const int* db = (n_in >= 3) ? (const int*)d_in[2] : nullptr;
    float* out = (float*)d_out;

    const int n_slices = in_sizes[0] / HW;  // 32768

    apply_mask_v8<<<n_slices, 64>>>(x, T, db, out);
}

// round 9
// speedup vs baseline: 1.0042x; 1.0042x over previous
#include <cuda_runtime.h>

// Apply_Mask v9 — v5 (best: 35.46us kernel, __ldcs reads, 2 warps/slice,
// 85% occ) with WRITE-THROUGH stores (st.global.wt): the 128MB write stream
// writes through L2 without allocating, so it stops sweeping the 134MB input
// out of the 126MB L2 between graph replays. Read hits rise, DRAM falls.
// (R6/R7 showed read-side hints regress; this targets the write side.)

#define H 32
#define W 32
#define HW 1024

__device__ __forceinline__ void st_wt(float4* p, float4 v) {
    asm volatile("st.global.wt.v4.f32 [%0], {%1,%2,%3,%4};"
                 :: "l"(p), "f"(v.x), "f"(v.y), "f"(v.z), "f"(v.w)
                 : "memory");
}

__global__ void __launch_bounds__(64)
apply_mask_v9(const float* __restrict__ x,
              const int* __restrict__ T,
              const int* __restrict__ drop_block_ptr,
              float* __restrict__ out)
{
    __shared__ unsigned skey[2];
    __shared__ unsigned sidx[2];

    const int tid = threadIdx.x;          // 0..63
    const int warp = tid >> 5;            // 0..1
    const int slice = blockIdx.x;
    const size_t base = (size_t)slice * HW;

    const float4* __restrict__ xin = reinterpret_cast<const float4*>(x + base);
    float4* __restrict__ o = reinterpret_cast<float4*>(out + base);

    // T load first, in flight alongside bulk loads (CTA-uniform value).
    const int t = __ldg(T + slice);

    // ---- front-batched bulk load: 4 x LDG.128 per lane, streaming ----
    float4 v[4];
#pragma unroll
    for (int j = 0; j < 4; j++)
        v[j] = __ldcs(xin + j * 64 + tid);

    if (t == 0) {
        // ---- copy path: no reduction, no barriers ----
#pragma unroll
        for (int j = 0; j < 4; j++)
            st_wt(o + j * 64 + tid, v[j]);
        return;
    }

    // ---- local max (pairwise tree), then warp REDUX on ordered key ----
    float m01 = fmaxf(fmaxf(fmaxf(v[0].x, v[0].y), fmaxf(v[0].z, v[0].w)),
                      fmaxf(fmaxf(v[1].x, v[1].y), fmaxf(v[1].z, v[1].w)));
    float m23 = fmaxf(fmaxf(fmaxf(v[2].x, v[2].y), fmaxf(v[2].z, v[2].w)),
                      fmaxf(fmaxf(v[3].x, v[3].y), fmaxf(v[3].z, v[3].w)));
    float m = fmaxf(m01, m23);

    unsigned u = __float_as_uint(m);
    unsigned key = u ^ (unsigned)(((int)u >> 31) | 0x80000000);
    key = __reduce_max_sync(0xffffffffu, key);

    if ((tid & 31) == 0) skey[warp] = key;
    __syncthreads();
    key = max(skey[0], skey[1]);

    unsigned mu = key ^ (unsigned)((~((int)key >> 31)) | 0x80000000);
    const float maxf = __uint_as_float(mu);

    // ---- first-occurrence index of maxf ----
    unsigned idx = HW;
    {
        const float* vf = &v[0].x;
#pragma unroll
        for (int j = 0; j < 4; j++) {
#pragma unroll
            for (int i = 0; i < 4; i++) {
                const unsigned e = (unsigned)((j * 64 + tid) * 4 + i);
                if (vf[j * 4 + i] == maxf) idx = min(idx, e);
            }
        }
    }
    idx = __reduce_min_sync(0xffffffffu, idx);

    if ((tid & 31) == 0) sidx[warp] = idx;
    __syncthreads();
    idx = min(sidx[0], sidx[1]);

    // ---- box + lambda ----
    const int mh = (int)(idx >> 5);
    const int mw = (int)(idx & (W - 1));
    const int db = drop_block_ptr ? *drop_block_ptr : 5;
    const int half = db >> 1;

    const int h1 = max(mh - half, 0);
    const int h2 = min(mh + half, H - 1);
    const int w1 = max(mw - half, 0);
    const int w2 = min(mw + half, W - 1);

    const int area = (h2 - h1 + 1) * (w2 - w1 + 1);
    const float lam = (float)HW / (float)(HW - area);

    // element e = (j*64 + tid)*4 + i  ->  row = j*8 + (tid>>3),
    //                                     col = (tid&7)*4 + i
    const int rbase = tid >> 3;
    const int cbase = (tid & 7) * 4;

    bool in_col[4];
#pragma unroll
    for (int i = 0; i < 4; i++)
        in_col[i] = (unsigned)(cbase + i - w1) <= (unsigned)(w2 - w1);

    float row_scale[4];  // scale when in_col true: 0 inside box, lam outside
#pragma unroll
    for (int j = 0; j < 4; j++) {
        const int r = j * 8 + rbase;
        const bool in_row = (unsigned)(r - h1) <= (unsigned)(h2 - h1);
        row_scale[j] = in_row ? 0.0f : lam;
    }

    // ---- scale + store ----
#pragma unroll
    for (int j = 0; j < 4; j++) {
        float4 w4;
        w4.x = v[j].x * (in_col[0] ? row_scale[j] : lam);
        w4.y = v[j].y * (in_col[1] ? row_scale[j] : lam);
        w4.z = v[j].z * (in_col[2] ? row_scale[j] : lam);
        w4.w = v[j].w * (in_col[3] ? row_scale[j] : lam);
        st_wt(o + j * 64 + tid, w4);
    }
}

extern "C" void kernel_launch(void* const* d_in, const int* in_sizes, int n_in,
                              void* d_out, int out_size)
{
    const float* x = (const float*)d_in[0];
    const int* T = (const int*)d_in[1];
    const int* db = (n_in >= 3) ? (const int*)d_in[2] : nullptr;
    float* out = (float*)d_out;

    const int n_slices = in_sizes[0] / HW;  // 32768

    apply_mask_v9<<<n_slices, 64>>>(x, T, db, out);
}

// round 10
// speedup vs baseline: 1.0252x; 1.0209x over previous
#include <cuda_runtime.h>

// Apply_Mask v10 — v5 memory structure (proven best: __ldcs reads, __stcs
// stores, 2 warps/slice, 64-thread CTA, 85% occ, 75.6% DRAM) with a fused
// single-barrier argmax: each thread packs (ordered max value, first index)
// into one u64, warp shuffle-max, ONE __syncthreads + 2-entry smem max.
// Removes a barrier round + a REDUX + post-barrier equality scan from the
// masked-warp critical path.

#define H 32
#define W 32
#define HW 1024

__global__ void __launch_bounds__(64)
apply_mask_v10(const float* __restrict__ x,
               const int* __restrict__ T,
               const int* __restrict__ drop_block_ptr,
               float* __restrict__ out)
{
    __shared__ unsigned long long sbest[2];

    const int tid = threadIdx.x;          // 0..63
    const int warp = tid >> 5;            // 0..1
    const int slice = blockIdx.x;
    const size_t base = (size_t)slice * HW;

    const float4* __restrict__ xin = reinterpret_cast<const float4*>(x + base);
    float4* __restrict__ o = reinterpret_cast<float4*>(out + base);

    // T load first, in flight alongside bulk loads (CTA-uniform value).
    const int t = __ldg(T + slice);

    // ---- front-batched bulk load: 4 x LDG.128 per lane, streaming ----
    float4 v[4];
#pragma unroll
    for (int j = 0; j < 4; j++)
        v[j] = __ldcs(xin + j * 64 + tid);

    if (t == 0) {
        // ---- copy path: no reduction, no barriers ----
#pragma unroll
        for (int j = 0; j < 4; j++)
            __stcs(o + j * 64 + tid, v[j]);
        return;
    }

    // ---- local max (pairwise tree) ----
    float m01 = fmaxf(fmaxf(fmaxf(v[0].x, v[0].y), fmaxf(v[0].z, v[0].w)),
                      fmaxf(fmaxf(v[1].x, v[1].y), fmaxf(v[1].z, v[1].w)));
    float m23 = fmaxf(fmaxf(fmaxf(v[2].x, v[2].y), fmaxf(v[2].z, v[2].w)),
                      fmaxf(fmaxf(v[3].x, v[3].y), fmaxf(v[3].z, v[3].w)));
    const float m = fmaxf(m01, m23);

    // ---- local first-occurrence index of m (indices ascend with j,i) ----
    unsigned lidx = HW;
    {
        const float* vf = &v[0].x;
#pragma unroll
        for (int j = 0; j < 4; j++) {
#pragma unroll
            for (int i = 0; i < 4; i++) {
                const unsigned e = (unsigned)((j * 64 + tid) * 4 + i);
                if (vf[j * 4 + i] == m) lidx = min(lidx, e);
            }
        }
    }

    // ---- pack (ordered value, inverted index); max-reduce => argmax with
    //      first-occurrence tie-break ----
    unsigned u = __float_as_uint(m);
    unsigned okey = u ^ (unsigned)(((int)u >> 31) | 0x80000000);
    unsigned long long best =
        ((unsigned long long)okey << 32) | (unsigned)(HW - 1 - lidx);

#pragma unroll
    for (int off = 16; off > 0; off >>= 1) {
        unsigned long long ob = __shfl_xor_sync(0xffffffffu, best, off);
        if (ob > best) best = ob;
    }

    if ((tid & 31) == 0) sbest[warp] = best;
    __syncthreads();
    {
        unsigned long long b0 = sbest[0];
        unsigned long long b1 = sbest[1];
        best = b0 > b1 ? b0 : b1;
    }

    const unsigned idx = (unsigned)(HW - 1) - (unsigned)(best & 0xffffffffu);

    // ---- box + lambda ----
    const int mh = (int)(idx >> 5);
    const int mw = (int)(idx & (W - 1));
    const int db = drop_block_ptr ? *drop_block_ptr : 5;
    const int half = db >> 1;

    const int h1 = max(mh - half, 0);
    const int h2 = min(mh + half, H - 1);
    const int w1 = max(mw - half, 0);
    const int w2 = min(mw + half, W - 1);

    const int area = (h2 - h1 + 1) * (w2 - w1 + 1);
    const float lam = (float)HW / (float)(HW - area);

    // element e = (j*64 + tid)*4 + i  ->  row = j*8 + (tid>>3),
    //                                     col = (tid&7)*4 + i
    const int rbase = tid >> 3;
    const int cbase = (tid & 7) * 4;

    bool in_col[4];
#pragma unroll
    for (int i = 0; i < 4; i++)
        in_col[i] = (unsigned)(cbase + i - w1) <= (unsigned)(w2 - w1);

    float row_scale[4];  // scale when in_col true: 0 inside box, lam outside
#pragma unroll
    for (int j = 0; j < 4; j++) {
        const int r = j * 8 + rbase;
        const bool in_row = (unsigned)(r - h1) <= (unsigned)(h2 - h1);
        row_scale[j] = in_row ? 0.0f : lam;
    }

    // ---- scale + store ----
#pragma unroll
    for (int j = 0; j < 4; j++) {
        float4 w4;
        w4.x = v[j].x * (in_col[0] ? row_scale[j] : lam);
        w4.y = v[j].y * (in_col[1] ? row_scale[j] : lam);
        w4.z = v[j].z * (in_col[2] ? row_scale[j] : lam);
        w4.w = v[j].w * (in_col[3] ? row_scale[j] : lam);
        __stcs(o + j * 64 + tid, w4);
    }
}

extern "C" void kernel_launch(void* const* d_in, const int* in_sizes, int n_in,
                              void* d_out, int out_size)
{
    const float* x = (const float*)d_in[0];
    const int* T = (const int*)d_in[1];
    const int* db = (n_in >= 3) ? (const int*)d_in[2] : nullptr;
    float* out = (float*)d_out;

    const int n_slices = in_sizes[0] / HW;  // 32768

    apply_mask_v10<<<n_slices, 64>>>(x, T, db, out);
}

// round 11
// speedup vs baseline: 1.0417x; 1.0161x over previous
#include <cuda_runtime.h>

// Apply_Mask v11 — composition of the two best measured configs:
//  * kernel structure of v10/v5 (2 warps per slice, 4x front-batched LDG.128,
//    __ldcs/__stcs streaming, fused u64 argmax, single sync) -> best kernel 35.5us
//  * grid shape of v4 (medium CTAs): 4 slices per 256-thread CTA, grid=8192
//    -> lower wall overhead than 32768 tiny CTAs (43.5 vs 44.4us measured).
// Per-slice sync uses NAMED barriers (bar.sync id,64): slice pairs in a CTA
// are fully decoupled; copy-path pairs (T==0, ~half) return with no barrier.

#define H 32
#define W 32
#define HW 1024
#define SLICES_PER_CTA 4

__global__ void __launch_bounds__(64 * SLICES_PER_CTA, 4)
apply_mask_v11(const float* __restrict__ x,
               const int* __restrict__ T,
               const int* __restrict__ drop_block_ptr,
               float* __restrict__ out)
{
    __shared__ unsigned long long sbest[SLICES_PER_CTA][2];

    const int tid = threadIdx.x;           // 0..255
    const int pair = tid >> 6;             // slice-pair within CTA: 0..3
    const int ptid = tid & 63;             // thread within pair: 0..63
    const int wip = (tid >> 5) & 1;        // warp within pair: 0..1
    const int slice = blockIdx.x * SLICES_PER_CTA + pair;
    const size_t base = (size_t)slice * HW;

    const float4* __restrict__ xin = reinterpret_cast<const float4*>(x + base);
    float4* __restrict__ o = reinterpret_cast<float4*>(out + base);

    // T load first, in flight alongside bulk loads (pair-uniform value).
    const int t = __ldg(T + slice);

    // ---- front-batched bulk load: 4 x LDG.128 per lane, streaming ----
    float4 v[4];
#pragma unroll
    for (int j = 0; j < 4; j++)
        v[j] = __ldcs(xin + j * 64 + ptid);

    if (t == 0) {
        // ---- copy path: no reduction, no barriers (pair-uniform branch) ----
#pragma unroll
        for (int j = 0; j < 4; j++)
            __stcs(o + j * 64 + ptid, v[j]);
        return;
    }

    // ---- local max (pairwise tree) ----
    float m01 = fmaxf(fmaxf(fmaxf(v[0].x, v[0].y), fmaxf(v[0].z, v[0].w)),
                      fmaxf(fmaxf(v[1].x, v[1].y), fmaxf(v[1].z, v[1].w)));
    float m23 = fmaxf(fmaxf(fmaxf(v[2].x, v[2].y), fmaxf(v[2].z, v[2].w)),
                      fmaxf(fmaxf(v[3].x, v[3].y), fmaxf(v[3].z, v[3].w)));
    const float m = fmaxf(m01, m23);

    // ---- local first-occurrence index of m ----
    unsigned lidx = HW;
    {
        const float* vf = &v[0].x;
#pragma unroll
        for (int j = 0; j < 4; j++) {
#pragma unroll
            for (int i = 0; i < 4; i++) {
                const unsigned e = (unsigned)((j * 64 + ptid) * 4 + i);
                if (vf[j * 4 + i] == m) lidx = min(lidx, e);
            }
        }
    }

    // ---- pack (ordered value, inverted index); max-reduce => argmax with
    //      first-occurrence tie-break ----
    unsigned u = __float_as_uint(m);
    unsigned okey = u ^ (unsigned)(((int)u >> 31) | 0x80000000);
    unsigned long long best =
        ((unsigned long long)okey << 32) | (unsigned)(HW - 1 - lidx);

#pragma unroll
    for (int off = 16; off > 0; off >>= 1) {
        unsigned long long ob = __shfl_xor_sync(0xffffffffu, best, off);
        if (ob > best) best = ob;
    }

    if ((ptid & 31) == 0) sbest[pair][wip] = best;
    // per-pair named barrier: 64 threads, ids 1..4 (0 reserved for CTA-wide)
    asm volatile("bar.sync %0, 64;" :: "r"(pair + 1) : "memory");
    {
        unsigned long long b0 = sbest[pair][0];
        unsigned long long b1 = sbest[pair][1];
        best = b0 > b1 ? b0 : b1;
    }

    const unsigned idx = (unsigned)(HW - 1) - (unsigned)(best & 0xffffffffu);

    // ---- box + lambda ----
    const int mh = (int)(idx >> 5);
    const int mw = (int)(idx & (W - 1));
    const int db = drop_block_ptr ? *drop_block_ptr : 5;
    const int half = db >> 1;

    const int h1 = max(mh - half, 0);
    const int h2 = min(mh + half, H - 1);
    const int w1 = max(mw - half, 0);
    const int w2 = min(mw + half, W - 1);

    const int area = (h2 - h1 + 1) * (w2 - w1 + 1);
    const float lam = (float)HW / (float)(HW - area);

    // element e = (j*64 + ptid)*4 + i  ->  row = j*8 + (ptid>>3),
    //                                      col = (ptid&7)*4 + i
    const int rbase = ptid >> 3;
    const int cbase = (ptid & 7) * 4;

    bool in_col[4];
#pragma unroll
    for (int i = 0; i < 4; i++)
        in_col[i] = (unsigned)(cbase + i - w1) <= (unsigned)(w2 - w1);

    float row_scale[4];  // scale when in_col true: 0 inside box, lam outside
#pragma unroll
    for (int j = 0; j < 4; j++) {
        const int r = j * 8 + rbase;
        const bool in_row = (unsigned)(r - h1) <= (unsigned)(h2 - h1);
        row_scale[j] = in_row ? 0.0f : lam;
    }

    // ---- scale + store ----
#pragma unroll
    for (int j = 0; j < 4; j++) {
        float4 w4;
        w4.x = v[j].x * (in_col[0] ? row_scale[j] : lam);
        w4.y = v[j].y * (in_col[1] ? row_scale[j] : lam);
        w4.z = v[j].z * (in_col[2] ? row_scale[j] : lam);
        w4.w = v[j].w * (in_col[3] ? row_scale[j] : lam);
        __stcs(o + j * 64 + ptid, w4);
    }
}

extern "C" void kernel_launch(void* const* d_in, const int* in_sizes, int n_in,
                              void* d_out, int out_size)
{
    const float* x = (const float*)d_in[0];
    const int* T = (const int*)d_in[1];
    const int* db = (n_in >= 3) ? (const int*)d_in[2] : nullptr;
    float* out = (float*)d_out;

    const int n_slices = in_sizes[0] / HW;           // 32768
    const int n_ctas = n_slices / SLICES_PER_CTA;    // 8192

    apply_mask_v11<<<n_ctas, 64 * SLICES_PER_CTA>>>(x, T, db, out);
}

// round 12
// speedup vs baseline: 1.0478x; 1.0059x over previous
#include <cuda_runtime.h>

// Apply_Mask v12 (final) — warp-per-slice (v4 shape: grid=4096, block=256,
// best measured wall 43.49us) with the fused packed-u64 argmax of v10:
// zero barriers, zero smem, reduction = 5 warp shuffles. __ldcs/__stcs
// streaming, T loaded first (in flight with the 8 front-batched LDG.128),
// T==0 warps (~half) take a pure copy path.
// Kernel is at the mixed read+write HBM roofline (~6TB/s, 75% of spec).

#define H 32
#define W 32
#define HW 1024
#define WPC 8

__global__ void __launch_bounds__(32 * WPC, 4)
apply_mask_v12(const float* __restrict__ x,
               const int* __restrict__ T,
               const int* __restrict__ drop_block_ptr,
               float* __restrict__ out)
{
    const int warp = threadIdx.x >> 5;
    const int lane = threadIdx.x & 31;
    const int slice = blockIdx.x * WPC + warp;
    const size_t base = (size_t)slice * HW;

    const float4* __restrict__ xin = reinterpret_cast<const float4*>(x + base);
    float4* __restrict__ o = reinterpret_cast<float4*>(out + base);

    // T load first, overlapping the bulk loads below (warp-uniform value).
    const int t = __ldg(T + slice);

    // ---- front-batched bulk load: 8 x LDG.128, streaming ----
    float4 v[8];
#pragma unroll
    for (int j = 0; j < 8; j++)
        v[j] = __ldcs(xin + j * 32 + lane);

    if (t == 0) {
        // ---- copy path: stores depend only on loads ----
#pragma unroll
        for (int j = 0; j < 8; j++)
            __stcs(o + j * 32 + lane, v[j]);
        return;
    }

    // ---- local max, pairwise tree ----
    float m01 = fmaxf(fmaxf(fmaxf(v[0].x, v[0].y), fmaxf(v[0].z, v[0].w)),
                      fmaxf(fmaxf(v[1].x, v[1].y), fmaxf(v[1].z, v[1].w)));
    float m23 = fmaxf(fmaxf(fmaxf(v[2].x, v[2].y), fmaxf(v[2].z, v[2].w)),
                      fmaxf(fmaxf(v[3].x, v[3].y), fmaxf(v[3].z, v[3].w)));
    float m45 = fmaxf(fmaxf(fmaxf(v[4].x, v[4].y), fmaxf(v[4].z, v[4].w)),
                      fmaxf(fmaxf(v[5].x, v[5].y), fmaxf(v[5].z, v[5].w)));
    float m67 = fmaxf(fmaxf(fmaxf(v[6].x, v[6].y), fmaxf(v[6].z, v[6].w)),
                      fmaxf(fmaxf(v[7].x, v[7].y), fmaxf(v[7].z, v[7].w)));
    const float m = fmaxf(fmaxf(m01, m23), fmaxf(m45, m67));

    // ---- local first-occurrence index of m ----
    unsigned lidx = HW;
    {
        const float* vf = &v[0].x;
#pragma unroll
        for (int j = 0; j < 8; j++) {
#pragma unroll
            for (int i = 0; i < 4; i++) {
                const unsigned e = (unsigned)(j * 128 + lane * 4 + i);
                if (vf[j * 4 + i] == m) lidx = min(lidx, e);
            }
        }
    }

    // ---- pack (ordered value, inverted index); 5-shuffle max-reduce =>
    //      argmax with first-occurrence tie-break. No barriers, no smem. ----
    unsigned u = __float_as_uint(m);
    unsigned okey = u ^ (unsigned)(((int)u >> 31) | 0x80000000);
    unsigned long long best =
        ((unsigned long long)okey << 32) | (unsigned)(HW - 1 - lidx);

#pragma unroll
    for (int off = 16; off > 0; off >>= 1) {
        unsigned long long ob = __shfl_xor_sync(0xffffffffu, best, off);
        if (ob > best) best = ob;
    }

    const unsigned idx = (unsigned)(HW - 1) - (unsigned)(best & 0xffffffffu);

    // ---- box + lambda ----
    const int mh = (int)(idx >> 5);
    const int mw = (int)(idx & (W - 1));
    const int db = drop_block_ptr ? *drop_block_ptr : 5;
    const int half = db >> 1;

    const int h1 = max(mh - half, 0);
    const int h2 = min(mh + half, H - 1);
    const int w1 = max(mw - half, 0);
    const int w2 = min(mw + half, W - 1);

    const int area = (h2 - h1 + 1) * (w2 - w1 + 1);
    const float lam = (float)HW / (float)(HW - area);

    // element e = j*128 + lane*4 + i -> row = j*4 + (lane>>3),
    //                                   col = (lane&7)*4 + i
    const int rbase = lane >> 3;
    const int cbase = (lane & 7) * 4;

    bool in_col[4];
#pragma unroll
    for (int i = 0; i < 4; i++)
        in_col[i] = (unsigned)(cbase + i - w1) <= (unsigned)(w2 - w1);

    float row_scale[8];  // scale when in_col true: 0 inside box, lam outside
#pragma unroll
    for (int j = 0; j < 8; j++) {
        const int r = j * 4 + rbase;
        const bool in_row = (unsigned)(r - h1) <= (unsigned)(h2 - h1);
        row_scale[j] = in_row ? 0.0f : lam;
    }

    // ---- scale + store ----
#pragma unroll
    for (int j = 0; j < 8; j++) {
        float4 w4;
        w4.x = v[j].x * (in_col[0] ? row_scale[j] : lam);
        w4.y = v[j].y * (in_col[1] ? row_scale[j] : lam);
        w4.z = v[j].z * (in_col[2] ? row_scale[j] : lam);
        w4.w = v[j].w * (in_col[3] ? row_scale[j] : lam);
        __stcs(o + j * 32 + lane, w4);
    }
}

extern "C" void kernel_launch(void* const* d_in, const int* in_sizes, int n_in,
                              void* d_out, int out_size)
{
    const float* x = (const float*)d_in[0];
    const int* T = (const int*)d_in[1];
    const int* db = (n_in >= 3) ? (const int*)d_in[2] : nullptr;
    float* out = (float*)d_out;

    const int n_slices = in_sizes[0] / HW;   // 32768
    const int n_ctas = n_slices / WPC;       // 4096

    apply_mask_v12<<<n_ctas, 32 * WPC>>>(x, T, db, out);
}